// round 10
// baseline (speedup 1.0000x reference)
#include <cuda_runtime.h>
#include <cstdint>

// R10: warp mma.sync bf16 3-split flash attention.
// vs R8/R9: ldmatrix fragments (verified in R9), NO cp.async staging,
// register-held K/V prefetch (LDG kt+1 consumed after GEMMs),
// double-buffered bf16 KV tiles -> ONE __syncthreads per kt,
// GEMM2 pair-interleaved (dep distance 4).

#define BM 128
#define BN 64
#define DH 64
#define NT 256
#define SQ 1024
#define KV_TILES 16

#define ROWB 144
#define SM_QHI 0
#define SM_QLO 18432
#define SM_KV0 36864
#define KVBUF  36864          // per-buffer: KHI,KLO,VHI,VLO each 9216
#define BK_HI 0
#define BK_LO 9216
#define BV_HI 18432
#define BV_LO 27648
#define SMEM_BYTES (SM_KV0 + 2 * KVBUF)   // 110592

static __device__ __forceinline__ uint32_t smem_u32(const void* p) {
    uint32_t a;
    asm("{ .reg .u64 t; cvta.to.shared.u64 t, %1; cvt.u32.u64 %0, t; }"
        : "=r"(a) : "l"(p));
    return a;
}
static __device__ __forceinline__ float ex2f(float x) {
    float y;
    asm("ex2.approx.ftz.f32 %0, %1;" : "=f"(y) : "f"(x));
    return y;
}
static __device__ __forceinline__ uint32_t cvt_bf2(float x0, float x1) {
    uint32_t r;
    asm("cvt.rn.bf16x2.f32 %0, %1, %2;" : "=r"(r) : "f"(x1), "f"(x0));
    return r;
}
static __device__ __forceinline__ void split2(float x0, float x1,
                                              uint32_t& h, uint32_t& l) {
    h = cvt_bf2(x0, x1);
    float h0 = __uint_as_float(h << 16);
    float h1 = __uint_as_float(h & 0xFFFF0000u);
    l = cvt_bf2(x0 - h0, x1 - h1);
}
static __device__ __forceinline__ void mma_bf16(float* c, const uint32_t* a,
                                                uint32_t b0, uint32_t b1) {
    asm volatile(
        "mma.sync.aligned.m16n8k16.row.col.f32.bf16.bf16.f32 "
        "{%0,%1,%2,%3}, {%4,%5,%6,%7}, {%8,%9}, {%0,%1,%2,%3};"
        : "+f"(c[0]), "+f"(c[1]), "+f"(c[2]), "+f"(c[3])
        : "r"(a[0]), "r"(a[1]), "r"(a[2]), "r"(a[3]), "r"(b0), "r"(b1));
}
static __device__ __forceinline__ void ldmx4(uint32_t* r, uint32_t addr) {
    asm volatile("ldmatrix.sync.aligned.m8n8.x4.shared.b16 {%0,%1,%2,%3}, [%4];"
        : "=r"(r[0]), "=r"(r[1]), "=r"(r[2]), "=r"(r[3]) : "r"(addr));
}
static __device__ __forceinline__ void ldmx4t(uint32_t* r, uint32_t addr) {
    asm volatile(
        "ldmatrix.sync.aligned.m8n8.x4.trans.shared.b16 {%0,%1,%2,%3}, [%4];"
        : "=r"(r[0]), "=r"(r[1]), "=r"(r[2]), "=r"(r[3]) : "r"(addr));
}
// convert 16 floats (4 float4) -> 32B hi + 32B lo at dsth/dstl
static __device__ __forceinline__ void conv16(const float4* v, char* dsth, char* dstl) {
    #pragma unroll
    for (int i = 0; i < 2; i++) {
        uint4 H, L;
        split2(v[2*i].x,   v[2*i].y,   H.x, L.x);
        split2(v[2*i].z,   v[2*i].w,   H.y, L.y);
        split2(v[2*i+1].x, v[2*i+1].y, H.z, L.z);
        split2(v[2*i+1].z, v[2*i+1].w, H.w, L.w);
        *(uint4*)(dsth + 16 * i) = H;
        *(uint4*)(dstl + 16 * i) = L;
    }
}

__global__ void __launch_bounds__(NT, 2) attn_mma(
    const float* __restrict__ Q, const float* __restrict__ K,
    const float* __restrict__ V, const int* __restrict__ mask,
    float* __restrict__ O)
{
    extern __shared__ char smem[];
    const int tid  = threadIdx.x;
    const int lane = tid & 31;
    const int warp = tid >> 5;
    const int g  = lane >> 2;
    const int tg = lane & 3;
    const int bh = blockIdx.y;
    const int b  = bh >> 4;
    const int qrow0 = blockIdx.x * BM;

    const float* Qg = Q + (size_t)bh * SQ * DH + (size_t)qrow0 * DH;
    const float* Kg = K + (size_t)bh * SQ * DH;
    const float* Vg = V + (size_t)bh * SQ * DH;
    float* Og = O + (size_t)bh * SQ * DH;

    // ---------------- masked fast path: O = mean(V) exactly ----------------
    if (mask[b] != 0) {
        float* smf = (float*)smem;
        const int tx = tid & 15, ty = tid >> 4;
        float4 acc = make_float4(0.f, 0.f, 0.f, 0.f);
        for (int n = ty; n < SQ; n += 16) {
            float4 v = *(const float4*)(Vg + (size_t)n * DH + tx * 4);
            acc.x += v.x; acc.y += v.y; acc.z += v.z; acc.w += v.w;
        }
        *(float4*)(smf + ty * 64 + tx * 4) = acc;
        __syncthreads();
        if (tid < 64) {
            float s = 0.f;
            #pragma unroll
            for (int gg = 0; gg < 16; gg++) s += smf[gg * 64 + tid];
            smf[1024 + tid] = s * (1.0f / 1024.0f);
        }
        __syncthreads();
        float4 ov = *(const float4*)(smf + 1024 + tx * 4);
        #pragma unroll
        for (int i = 0; i < 8; i++)
            *(float4*)(Og + (size_t)(qrow0 + ty + i * 16) * DH + tx * 4) = ov;
        return;
    }
    // ------------------------------------------------------------------------

    const uint32_t sb = smem_u32(smem);
    const int krow = tid >> 2, kq = tid & 3;     // K/V ownership: row, 16-float chunk
    const float* kgp = Kg + (size_t)krow * DH + kq * 16;
    const float* vgp = Vg + (size_t)krow * DH + kq * 16;
    const uint32_t cvo = krow * ROWB + kq * 32;  // bf16 dst offset within tile

    // ---- prologue: raw K/V(0) -> regs; Q convert; convert(0) -> buf0 ----
    float4 rk[4], rv[4];
    #pragma unroll
    for (int i = 0; i < 4; i++) { rk[i] = *(const float4*)(kgp + 4 * i); }
    #pragma unroll
    for (int i = 0; i < 4; i++) { rv[i] = *(const float4*)(vgp + 4 * i); }

    {
        int row = tid >> 1, hf = tid & 1;
        const float* qr = Qg + (size_t)row * DH + hf * 32;
        float4 qv[4];
        #pragma unroll
        for (int i = 0; i < 4; i++) qv[i] = *(const float4*)(qr + i * 8 + (i & 1) * 0 + (i >> 1) * 0 + 0 + 4 * i * 0 + 0);
        // (load 16 consecutive floats: qr + 0,4,8,12)
        qv[0] = *(const float4*)(qr + 0);
        qv[1] = *(const float4*)(qr + 4);
        qv[2] = *(const float4*)(qr + 8);
        qv[3] = *(const float4*)(qr + 12);
        conv16(qv, smem + SM_QHI + row * ROWB + hf * 64,
                   smem + SM_QLO + row * ROWB + hf * 64);
        float4 qv2[4];
        qv2[0] = *(const float4*)(qr + 16);
        qv2[1] = *(const float4*)(qr + 20);
        qv2[2] = *(const float4*)(qr + 24);
        qv2[3] = *(const float4*)(qr + 28);
        conv16(qv2, smem + SM_QHI + row * ROWB + hf * 64 + 32,
                    smem + SM_QLO + row * ROWB + hf * 64 + 32);
    }
    conv16(rk, smem + SM_KV0 + BK_HI + cvo, smem + SM_KV0 + BK_LO + cvo);
    conv16(rv, smem + SM_KV0 + BV_HI + cvo, smem + SM_KV0 + BV_LO + cvo);
    __syncthreads();

    const float C1 = 0.18033688011112042f;   // 0.125 * log2(e)
    const float C2 = 11.541560327111707f;    // 8 * log2(e) fixed shift
    const int m0 = warp * 16;

    float Oc[8][4];
    #pragma unroll
    for (int t = 0; t < 8; t++)
        #pragma unroll
        for (int c = 0; c < 4; c++) Oc[t][c] = 0.f;
    float l0 = 0.f, l1 = 0.f;

    const uint32_t qfb = sb + SM_QHI + (m0 + (lane & 15)) * ROWB + (lane >> 4) * 16;
    #define QLOFF (SM_QLO - SM_QHI)

    #pragma unroll 2
    for (int kt = 0; kt < KV_TILES; kt++) {
        const uint32_t bufb = sb + SM_KV0 + (kt & 1) * KVBUF;
        const uint32_t nbufo = SM_KV0 + ((kt + 1) & 1) * KVBUF;
        const uint32_t kfb  = bufb + BK_HI + (lane & 7) * ROWB + (lane >> 3) * 16;
        const uint32_t vfb  = bufb + BV_HI + (lane & 15) * ROWB + (lane >> 4) * 16;

        // ---- prefetch raw K/V(kt+1) into registers (consumed after GEMMs) ----
        if (kt + 1 < KV_TILES) {
            const float* kp = kgp + (size_t)(kt + 1) * BN * DH;
            const float* vp = vgp + (size_t)(kt + 1) * BN * DH;
            #pragma unroll
            for (int i = 0; i < 4; i++) rk[i] = *(const float4*)(kp + 4 * i);
            #pragma unroll
            for (int i = 0; i < 4; i++) rv[i] = *(const float4*)(vp + 4 * i);
        }

        // ---- GEMM1: S = Q @ K^T (3-split) ----
        float S[8][4];
        #pragma unroll
        for (int t = 0; t < 8; t++)
            #pragma unroll
            for (int c = 0; c < 4; c++) S[t][c] = 0.f;

        #pragma unroll
        for (int kcp = 0; kcp < 2; kcp++) {
            uint32_t qh0[4], qh1[4], ql0[4], ql1[4];
            ldmx4(qh0, qfb + kcp * 64);
            ldmx4(qh1, qfb + kcp * 64 + 32);
            ldmx4(ql0, qfb + QLOFF + kcp * 64);
            ldmx4(ql1, qfb + QLOFF + kcp * 64 + 32);
            #pragma unroll
            for (int nt = 0; nt < 8; nt++) {
                uint32_t kh[4], kl[4];
                ldmx4(kh, kfb + nt * (8 * ROWB) + kcp * 64);
                ldmx4(kl, kfb + (BK_LO - BK_HI) + nt * (8 * ROWB) + kcp * 64);
                mma_bf16(S[nt], qh0, kh[0], kh[1]);
                mma_bf16(S[nt], qh0, kl[0], kl[1]);
                mma_bf16(S[nt], ql0, kh[0], kh[1]);
                mma_bf16(S[nt], qh1, kh[2], kh[3]);
                mma_bf16(S[nt], qh1, kl[2], kl[3]);
                mma_bf16(S[nt], ql1, kh[2], kh[3]);
            }
        }

        // ---- softmax (fixed shift) + in-register P fragments ----
        uint32_t ah[4][4], al[4][4];
        #pragma unroll
        for (int nt = 0; nt < 8; nt++) {
            float p0 = ex2f(S[nt][0] * C1 - C2);
            float p1 = ex2f(S[nt][1] * C1 - C2);
            float p2 = ex2f(S[nt][2] * C1 - C2);
            float p3 = ex2f(S[nt][3] * C1 - C2);
            l0 += p0 + p1;
            l1 += p2 + p3;
            int kc = nt >> 1, o = (nt & 1) * 2;
            split2(p0, p1, ah[kc][o],     al[kc][o]);
            split2(p2, p3, ah[kc][o + 1], al[kc][o + 1]);
        }

        // ---- convert raw K(kt+1) -> next buffer (frees rk regs) ----
        if (kt + 1 < KV_TILES)
            conv16(rk, smem + nbufo + BK_HI + cvo, smem + nbufo + BK_LO + cvo);

        // ---- GEMM2: O += P @ V, pair-interleaved (dep distance 4) ----
        #pragma unroll
        for (int kc = 0; kc < 4; kc++) {
            #pragma unroll
            for (int dp = 0; dp < 2; dp++) {
                uint32_t vaA = kc * 16 * ROWB + (2 * dp) * 32;
                uint32_t vaB = vaA + 32;
                uint32_t hA[4], hB[4], qA[4], qB[4];
                ldmx4t(hA, vfb + vaA);
                ldmx4t(hB, vfb + vaB);
                ldmx4t(qA, vfb + (BV_LO - BV_HI) + vaA);
                ldmx4t(qB, vfb + (BV_LO - BV_HI) + vaB);
                float* c0 = Oc[4 * dp + 0];
                float* c1 = Oc[4 * dp + 1];
                float* c2 = Oc[4 * dp + 2];
                float* c3 = Oc[4 * dp + 3];
                mma_bf16(c0, ah[kc], hA[0], hA[1]);
                mma_bf16(c1, ah[kc], hA[2], hA[3]);
                mma_bf16(c2, ah[kc], hB[0], hB[1]);
                mma_bf16(c3, ah[kc], hB[2], hB[3]);
                mma_bf16(c0, ah[kc], qA[0], qA[1]);
                mma_bf16(c1, ah[kc], qA[2], qA[3]);
                mma_bf16(c2, ah[kc], qB[0], qB[1]);
                mma_bf16(c3, ah[kc], qB[2], qB[3]);
                mma_bf16(c0, al[kc], hA[0], hA[1]);
                mma_bf16(c1, al[kc], hA[2], hA[3]);
                mma_bf16(c2, al[kc], hB[0], hB[1]);
                mma_bf16(c3, al[kc], hB[2], hB[3]);
            }
        }

        // ---- convert raw V(kt+1) -> next buffer ----
        if (kt + 1 < KV_TILES)
            conv16(rv, smem + nbufo + BV_HI + cvo, smem + nbufo + BV_LO + cvo);

        __syncthreads();   // single sync per kt
    }

    // ---- epilogue ----
    l0 += __shfl_xor_sync(0xffffffffu, l0, 1);
    l0 += __shfl_xor_sync(0xffffffffu, l0, 2);
    l1 += __shfl_xor_sync(0xffffffffu, l1, 1);
    l1 += __shfl_xor_sync(0xffffffffu, l1, 2);
    float inv0 = 1.0f / l0, inv1 = 1.0f / l1;

    float* r0p = Og + (size_t)(qrow0 + m0 + g) * DH + 2 * tg;
    float* r1p = r0p + 8 * (size_t)DH;
    #pragma unroll
    for (int dt = 0; dt < 8; dt++) {
        *(float2*)(r0p + dt * 8) = make_float2(Oc[dt][0] * inv0, Oc[dt][1] * inv0);
        *(float2*)(r1p + dt * 8) = make_float2(Oc[dt][2] * inv1, Oc[dt][3] * inv1);
    }
}

extern "C" void kernel_launch(void* const* d_in, const int* in_sizes, int n_in,
                              void* d_out, int out_size)
{
    const float* Q = (const float*)d_in[0];
    const float* K = (const float*)d_in[1];
    const float* V = (const float*)d_in[2];
    const int* mask = (const int*)d_in[3];
    float* O = (float*)d_out;

    cudaFuncSetAttribute(attn_mma,
                         cudaFuncAttributeMaxDynamicSharedMemorySize, SMEM_BYTES);

    dim3 grid(SQ / BM, 8 * 16);   // (8, 128)
    attn_mma<<<grid, NT, SMEM_BYTES>>>(Q, K, V, mask, O);
}

// round 11
// speedup vs baseline: 1.0850x; 1.0850x over previous
#include <cuda_runtime.h>
#include <cstdint>

// R11: R8 skeleton (best: 141.8us) + two zero-cost changes:
// (a) GEMM1 fragments via ldmatrix.x4 (verified addressing from R9;
//     160 scalar LDS -> 24 ldmatrix per warp/kt, ~40% fewer L1 wavefronts);
// (b) prefetch.global.L2 for kt+1 K/V (hides DRAM latency, 0 regs / 0 smem
//     -- the R9/R10 pipelining attempts regressed via smem traffic / spills).
// Numerics unchanged: bf16 hi/lo 3-split both GEMMs, fixed-shift softmax.

#define BM 128
#define BN 64
#define DH 64
#define NT 256
#define SQ 1024
#define KV_TILES 16

#define ROWB 144
#define SM_QHI 0
#define SM_QLO 18432
#define SM_KHI 36864
#define SM_KLO 46080
#define SM_VHI 55296
#define SM_VLO 64512
#define SMEM_BYTES 73728

static __device__ __forceinline__ uint32_t smem_u32(const void* p) {
    uint32_t a;
    asm("{ .reg .u64 t; cvta.to.shared.u64 t, %1; cvt.u32.u64 %0, t; }"
        : "=r"(a) : "l"(p));
    return a;
}
static __device__ __forceinline__ float ex2f(float x) {
    float y;
    asm("ex2.approx.ftz.f32 %0, %1;" : "=f"(y) : "f"(x));
    return y;
}
static __device__ __forceinline__ uint32_t cvt_bf2(float x0, float x1) {
    uint32_t r;
    asm("cvt.rn.bf16x2.f32 %0, %1, %2;" : "=r"(r) : "f"(x1), "f"(x0));
    return r;
}
static __device__ __forceinline__ void split2(float x0, float x1,
                                              uint32_t& h, uint32_t& l) {
    h = cvt_bf2(x0, x1);
    float h0 = __uint_as_float(h << 16);
    float h1 = __uint_as_float(h & 0xFFFF0000u);
    l = cvt_bf2(x0 - h0, x1 - h1);
}
static __device__ __forceinline__ void mma_bf16(float* c, const uint32_t* a,
                                                uint32_t b0, uint32_t b1) {
    asm volatile(
        "mma.sync.aligned.m16n8k16.row.col.f32.bf16.bf16.f32 "
        "{%0,%1,%2,%3}, {%4,%5,%6,%7}, {%8,%9}, {%0,%1,%2,%3};"
        : "+f"(c[0]), "+f"(c[1]), "+f"(c[2]), "+f"(c[3])
        : "r"(a[0]), "r"(a[1]), "r"(a[2]), "r"(a[3]), "r"(b0), "r"(b1));
}
static __device__ __forceinline__ void ldmx4(uint32_t* r, uint32_t addr) {
    asm volatile("ldmatrix.sync.aligned.m8n8.x4.shared.b16 {%0,%1,%2,%3}, [%4];"
        : "=r"(r[0]), "=r"(r[1]), "=r"(r[2]), "=r"(r[3]) : "r"(addr));
}
static __device__ __forceinline__ void ldmx4t(uint32_t& r0, uint32_t& r1,
                                              uint32_t& r2, uint32_t& r3,
                                              uint32_t addr) {
    asm volatile(
        "ldmatrix.sync.aligned.m8n8.x4.trans.shared.b16 {%0,%1,%2,%3}, [%4];"
        : "=r"(r0), "=r"(r1), "=r"(r2), "=r"(r3) : "r"(addr));
}
static __device__ __forceinline__ void pf_l2(const void* p) {
    asm volatile("prefetch.global.L2 [%0];" :: "l"(p));
}

__global__ void __launch_bounds__(NT, 2) attn_mma(
    const float* __restrict__ Q, const float* __restrict__ K,
    const float* __restrict__ V, const int* __restrict__ mask,
    float* __restrict__ O)
{
    extern __shared__ char smem[];
    const int tid  = threadIdx.x;
    const int lane = tid & 31;
    const int warp = tid >> 5;
    const int g  = lane >> 2;
    const int tg = lane & 3;
    const int bh = blockIdx.y;
    const int b  = bh >> 4;
    const int qrow0 = blockIdx.x * BM;

    const float* Qg = Q + (size_t)bh * SQ * DH + (size_t)qrow0 * DH;
    const float* Kg = K + (size_t)bh * SQ * DH;
    const float* Vg = V + (size_t)bh * SQ * DH;
    float* Og = O + (size_t)bh * SQ * DH;

    // ---------------- masked fast path: O = mean(V) exactly ----------------
    if (mask[b] != 0) {
        float* smf = (float*)smem;
        const int tx = tid & 15, ty = tid >> 4;
        float4 acc = make_float4(0.f, 0.f, 0.f, 0.f);
        for (int n = ty; n < SQ; n += 16) {
            float4 v = *(const float4*)(Vg + (size_t)n * DH + tx * 4);
            acc.x += v.x; acc.y += v.y; acc.z += v.z; acc.w += v.w;
        }
        *(float4*)(smf + ty * 64 + tx * 4) = acc;
        __syncthreads();
        if (tid < 64) {
            float s = 0.f;
            #pragma unroll
            for (int gg = 0; gg < 16; gg++) s += smf[gg * 64 + tid];
            smf[1024 + tid] = s * (1.0f / 1024.0f);
        }
        __syncthreads();
        float4 ov = *(const float4*)(smf + 1024 + tx * 4);
        #pragma unroll
        for (int i = 0; i < 8; i++)
            *(float4*)(Og + (size_t)(qrow0 + ty + i * 16) * DH + tx * 4) = ov;
        return;
    }
    // ------------------------------------------------------------------------

    const uint32_t sb = smem_u32(smem);

    // ---- Q -> bf16 hi/lo smem ----
    {
        int row = tid >> 1, hf = tid & 1;
        const float* qr = Qg + (size_t)row * DH + hf * 32;
        char* qh = smem + SM_QHI + row * ROWB + hf * 64;
        char* ql = smem + SM_QLO + row * ROWB + hf * 64;
        #pragma unroll
        for (int i = 0; i < 4; i++) {
            float4 x = *(const float4*)(qr + i * 8);
            float4 y = *(const float4*)(qr + i * 8 + 4);
            uint4 H, L;
            split2(x.x, x.y, H.x, L.x); split2(x.z, x.w, H.y, L.y);
            split2(y.x, y.y, H.z, L.z); split2(y.z, y.w, H.w, L.w);
            *(uint4*)(qh + i * 16) = H;
            *(uint4*)(ql + i * 16) = L;
        }
    }

    const float C1 = 0.18033688011112042f;   // 0.125 * log2(e)
    const float C2 = 11.541560327111707f;    // 8 * log2(e) fixed shift
    const int m0 = warp * 16;

    float Oc[8][4];
    #pragma unroll
    for (int t = 0; t < 8; t++)
        #pragma unroll
        for (int c = 0; c < 4; c++) Oc[t][c] = 0.f;
    float l0 = 0.f, l1 = 0.f;

    // fragment base addresses (constant over kt)
    const uint32_t qfb  = sb + SM_QHI + (m0 + (lane & 15)) * ROWB + (lane >> 4) * 16;
    const uint32_t kfb  = sb + SM_KHI + (lane & 7) * ROWB + (lane >> 3) * 16;
    const uint32_t sbVh = sb + SM_VHI + (lane & 15) * ROWB + (lane >> 4) * 16;
    #define QLOFF (SM_QLO - SM_QHI)
    #define KLOFF (SM_KLO - SM_KHI)
    #define VLOFF (SM_VLO - SM_VHI)

    const int krow = tid >> 2, kq = tid & 3;   // K/V conversion ownership

    for (int kt = 0; kt < KV_TILES; kt++) {
        if (kt > 0) __syncthreads();   // prior GEMM reads done before overwrite

        // ---- K,V tiles -> bf16 hi/lo smem (direct LDG, as R8) ----
        {
            const float* kr = Kg + (size_t)(kt * BN + krow) * DH + kq * 16;
            const float* vr = Vg + (size_t)(kt * BN + krow) * DH + kq * 16;
            char* kh = smem + SM_KHI + krow * ROWB + kq * 32;
            char* kl = smem + SM_KLO + krow * ROWB + kq * 32;
            char* vh = smem + SM_VHI + krow * ROWB + kq * 32;
            char* vl = smem + SM_VLO + krow * ROWB + kq * 32;
            #pragma unroll
            for (int i = 0; i < 2; i++) {
                float4 x = *(const float4*)(kr + i * 8);
                float4 y = *(const float4*)(kr + i * 8 + 4);
                uint4 H, L;
                split2(x.x, x.y, H.x, L.x); split2(x.z, x.w, H.y, L.y);
                split2(y.x, y.y, H.z, L.z); split2(y.z, y.w, H.w, L.w);
                *(uint4*)(kh + i * 16) = H;
                *(uint4*)(kl + i * 16) = L;
                x = *(const float4*)(vr + i * 8);
                y = *(const float4*)(vr + i * 8 + 4);
                split2(x.x, x.y, H.x, L.x); split2(x.z, x.w, H.y, L.y);
                split2(y.x, y.y, H.z, L.z); split2(y.z, y.w, H.w, L.w);
                *(uint4*)(vh + i * 16) = H;
                *(uint4*)(vl + i * 16) = L;
            }
        }
        __syncthreads();

        // ---- prefetch kt+1 K/V lines into L2 (0 regs, 0 smem) ----
        if (kt + 1 < KV_TILES) {
            pf_l2(Kg + (size_t)((kt + 1) * BN + krow) * DH + kq * 16);
            pf_l2(Vg + (size_t)((kt + 1) * BN + krow) * DH + kq * 16);
        }

        // ---- GEMM1: S = Q @ K^T (3-split, ldmatrix fragments) ----
        float S[8][4];
        #pragma unroll
        for (int t = 0; t < 8; t++)
            #pragma unroll
            for (int c = 0; c < 4; c++) S[t][c] = 0.f;

        #pragma unroll
        for (int kcp = 0; kcp < 2; kcp++) {
            uint32_t qh0[4], qh1[4], ql0[4], ql1[4];
            ldmx4(qh0, qfb + kcp * 64);
            ldmx4(qh1, qfb + kcp * 64 + 32);
            ldmx4(ql0, qfb + QLOFF + kcp * 64);
            ldmx4(ql1, qfb + QLOFF + kcp * 64 + 32);
            #pragma unroll
            for (int nt = 0; nt < 8; nt++) {
                uint32_t kh[4], kl[4];
                ldmx4(kh, kfb + nt * (8 * ROWB) + kcp * 64);
                ldmx4(kl, kfb + KLOFF + nt * (8 * ROWB) + kcp * 64);
                mma_bf16(S[nt], qh0, kh[0], kh[1]);
                mma_bf16(S[nt], qh0, kl[0], kl[1]);
                mma_bf16(S[nt], ql0, kh[0], kh[1]);
                mma_bf16(S[nt], qh1, kh[2], kh[3]);
                mma_bf16(S[nt], qh1, kl[2], kl[3]);
                mma_bf16(S[nt], ql1, kh[2], kh[3]);
            }
        }

        // ---- softmax (fixed shift) + in-register P fragments ----
        uint32_t ah[4][4], al[4][4];
        #pragma unroll
        for (int nt = 0; nt < 8; nt++) {
            float p0 = ex2f(S[nt][0] * C1 - C2);
            float p1 = ex2f(S[nt][1] * C1 - C2);
            float p2 = ex2f(S[nt][2] * C1 - C2);
            float p3 = ex2f(S[nt][3] * C1 - C2);
            l0 += p0 + p1;
            l1 += p2 + p3;
            int kc = nt >> 1, o = (nt & 1) * 2;
            split2(p0, p1, ah[kc][o],     al[kc][o]);
            split2(p2, p3, ah[kc][o + 1], al[kc][o + 1]);
        }

        // ---- GEMM2: O += P @ V (V via ldmatrix.trans) ----
        #pragma unroll
        for (int kc = 0; kc < 4; kc++) {
            #pragma unroll
            for (int dtp = 0; dtp < 4; dtp++) {
                uint32_t va = kc * 16 * ROWB + dtp * 32;
                uint32_t h0, h1, h2, h3, q0, q1, q2, q3;
                ldmx4t(h0, h1, h2, h3, sbVh + va);
                ldmx4t(q0, q1, q2, q3, sbVh + VLOFF + va);
                mma_bf16(Oc[2 * dtp],     ah[kc], h0, h1);
                mma_bf16(Oc[2 * dtp + 1], ah[kc], h2, h3);
                mma_bf16(Oc[2 * dtp],     ah[kc], q0, q1);
                mma_bf16(Oc[2 * dtp + 1], ah[kc], q2, q3);
                mma_bf16(Oc[2 * dtp],     al[kc], h0, h1);
                mma_bf16(Oc[2 * dtp + 1], al[kc], h2, h3);
            }
        }
    }

    // ---- epilogue ----
    l0 += __shfl_xor_sync(0xffffffffu, l0, 1);
    l0 += __shfl_xor_sync(0xffffffffu, l0, 2);
    l1 += __shfl_xor_sync(0xffffffffu, l1, 1);
    l1 += __shfl_xor_sync(0xffffffffu, l1, 2);
    float inv0 = 1.0f / l0, inv1 = 1.0f / l1;

    float* r0p = Og + (size_t)(qrow0 + m0 + g) * DH + 2 * tg;
    float* r1p = r0p + 8 * (size_t)DH;
    #pragma unroll
    for (int dt = 0; dt < 8; dt++) {
        *(float2*)(r0p + dt * 8) = make_float2(Oc[dt][0] * inv0, Oc[dt][1] * inv0);
        *(float2*)(r1p + dt * 8) = make_float2(Oc[dt][2] * inv1, Oc[dt][3] * inv1);
    }
}

extern "C" void kernel_launch(void* const* d_in, const int* in_sizes, int n_in,
                              void* d_out, int out_size)
{
    const float* Q = (const float*)d_in[0];
    const float* K = (const float*)d_in[1];
    const float* V = (const float*)d_in[2];
    const int* mask = (const int*)d_in[3];
    float* O = (float*)d_out;

    cudaFuncSetAttribute(attn_mma,
                         cudaFuncAttributeMaxDynamicSharedMemorySize, SMEM_BYTES);

    dim3 grid(SQ / BM, 8 * 16);   // (8, 128)
    attn_mma<<<grid, NT, SMEM_BYTES>>>(Q, K, V, mask, O);
}

// round 12
// speedup vs baseline: 1.1729x; 1.0811x over previous
#include <cuda_runtime.h>
#include <cuda_bf16.h>
#include <cstdint>

// R12: two-kernel design.
//  K1 conv_kv: K,V fp32 -> bf16 hi/lo in __device__ global scratch, ONCE per
//     element (was 8x redundant per-CTA), masked batches skipped.
//  K2 attn_mma: R8 skeleton, loop convert phase replaced by cp.async.cg of
//     pre-converted bf16 tiles into double-buffered smem; one sync/kt;
//     tile kt+1 in flight during compute of kt (0 extra registers).
// Numerics unchanged: bf16 hi/lo 3-split both GEMMs, fixed-shift softmax.

#define BM 128
#define BN 64
#define DH 64
#define NT 256
#define SQ 1024
#define KV_TILES 16
#define TOTE (8 * 16 * 1024 * 64)       // elems per tensor

__device__ __nv_bfloat16 g_khi[TOTE];
__device__ __nv_bfloat16 g_klo[TOTE];
__device__ __nv_bfloat16 g_vhi[TOTE];
__device__ __nv_bfloat16 g_vlo[TOTE];

#define ROWB 144
#define SM_QHI 0
#define SM_QLO 18432
#define SM_KV0 36864
#define KVBUF  36864        // per buffer: KHI 0, KLO 9216, VHI 18432, VLO 27648
#define BK_HI 0
#define BK_LO 9216
#define BV_HI 18432
#define BV_LO 27648
#define SMEM_BYTES (SM_KV0 + 2 * KVBUF)   // 110592

static __device__ __forceinline__ uint32_t smem_u32(const void* p) {
    uint32_t a;
    asm("{ .reg .u64 t; cvta.to.shared.u64 t, %1; cvt.u32.u64 %0, t; }"
        : "=r"(a) : "l"(p));
    return a;
}
static __device__ __forceinline__ float ex2f(float x) {
    float y;
    asm("ex2.approx.ftz.f32 %0, %1;" : "=f"(y) : "f"(x));
    return y;
}
static __device__ __forceinline__ uint32_t cvt_bf2(float x0, float x1) {
    uint32_t r;
    asm("cvt.rn.bf16x2.f32 %0, %1, %2;" : "=r"(r) : "f"(x1), "f"(x0));
    return r;
}
static __device__ __forceinline__ void split2(float x0, float x1,
                                              uint32_t& h, uint32_t& l) {
    h = cvt_bf2(x0, x1);
    float h0 = __uint_as_float(h << 16);
    float h1 = __uint_as_float(h & 0xFFFF0000u);
    l = cvt_bf2(x0 - h0, x1 - h1);
}
static __device__ __forceinline__ void mma_bf16(float* c, const uint32_t* a,
                                                uint32_t b0, uint32_t b1) {
    asm volatile(
        "mma.sync.aligned.m16n8k16.row.col.f32.bf16.bf16.f32 "
        "{%0,%1,%2,%3}, {%4,%5,%6,%7}, {%8,%9}, {%0,%1,%2,%3};"
        : "+f"(c[0]), "+f"(c[1]), "+f"(c[2]), "+f"(c[3])
        : "r"(a[0]), "r"(a[1]), "r"(a[2]), "r"(a[3]), "r"(b0), "r"(b1));
}
static __device__ __forceinline__ void ldmx4(uint32_t* r, uint32_t addr) {
    asm volatile("ldmatrix.sync.aligned.m8n8.x4.shared.b16 {%0,%1,%2,%3}, [%4];"
        : "=r"(r[0]), "=r"(r[1]), "=r"(r[2]), "=r"(r[3]) : "r"(addr));
}
static __device__ __forceinline__ void ldmx4t(uint32_t& r0, uint32_t& r1,
                                              uint32_t& r2, uint32_t& r3,
                                              uint32_t addr) {
    asm volatile(
        "ldmatrix.sync.aligned.m8n8.x4.trans.shared.b16 {%0,%1,%2,%3}, [%4];"
        : "=r"(r0), "=r"(r1), "=r"(r2), "=r"(r3) : "r"(addr));
}
static __device__ __forceinline__ void cp16(uint32_t dst, const void* src) {
    uint64_t g;
    asm("cvta.to.global.u64 %0, %1;" : "=l"(g) : "l"(src));
    asm volatile("cp.async.cg.shared.global [%0], [%1], 16;"
                 :: "r"(dst), "l"(g) : "memory");
}
#define CP_COMMIT() asm volatile("cp.async.commit_group;" ::: "memory")
#define CP_WAIT0()  asm volatile("cp.async.wait_group 0;" ::: "memory")

// ---------------- kernel 1: K/V fp32 -> bf16 hi/lo (once) ----------------
__global__ void __launch_bounds__(256) conv_kv(
    const float* __restrict__ K, const float* __restrict__ V,
    const int* __restrict__ mask)
{
    const int bidx = blockIdx.x;            // 0..8191; <4096 = K, else V
    const int tb   = bidx & 4095;           // block within tensor
    const int b    = tb >> 9;               // 512 blocks per batch
    if (mask[b] != 0) return;               // masked batches never read
    const size_t e = ((size_t)tb * 256 + threadIdx.x) * 8;
    const bool isK = bidx < 4096;
    const float* src = (isK ? K : V) + e;
    __nv_bfloat16* dh = (isK ? g_khi : g_vhi) + e;
    __nv_bfloat16* dl = (isK ? g_klo : g_vlo) + e;
    float4 a = *(const float4*)(src);
    float4 c = *(const float4*)(src + 4);
    uint4 H, L;
    split2(a.x, a.y, H.x, L.x); split2(a.z, a.w, H.y, L.y);
    split2(c.x, c.y, H.z, L.z); split2(c.z, c.w, H.w, L.w);
    *(uint4*)dh = H;
    *(uint4*)dl = L;
}

// ---------------- kernel 2: attention ----------------
__global__ void __launch_bounds__(NT, 2) attn_mma(
    const float* __restrict__ Q, const float* __restrict__ V,
    const int* __restrict__ mask, float* __restrict__ O)
{
    extern __shared__ char smem[];
    const int tid  = threadIdx.x;
    const int lane = tid & 31;
    const int warp = tid >> 5;
    const int g  = lane >> 2;
    const int tg = lane & 3;
    const int bh = blockIdx.y;
    const int b  = bh >> 4;
    const int qrow0 = blockIdx.x * BM;

    const float* Qg = Q + (size_t)bh * SQ * DH + (size_t)qrow0 * DH;
    const float* Vg = V + (size_t)bh * SQ * DH;
    float* Og = O + (size_t)bh * SQ * DH;

    // ---------------- masked fast path: O = mean(V) exactly ----------------
    if (mask[b] != 0) {
        float* smf = (float*)smem;
        const int tx = tid & 15, ty = tid >> 4;
        float4 acc = make_float4(0.f, 0.f, 0.f, 0.f);
        for (int n = ty; n < SQ; n += 16) {
            float4 v = *(const float4*)(Vg + (size_t)n * DH + tx * 4);
            acc.x += v.x; acc.y += v.y; acc.z += v.z; acc.w += v.w;
        }
        *(float4*)(smf + ty * 64 + tx * 4) = acc;
        __syncthreads();
        if (tid < 64) {
            float s = 0.f;
            #pragma unroll
            for (int gg = 0; gg < 16; gg++) s += smf[gg * 64 + tid];
            smf[1024 + tid] = s * (1.0f / 1024.0f);
        }
        __syncthreads();
        float4 ov = *(const float4*)(smf + 1024 + tx * 4);
        #pragma unroll
        for (int i = 0; i < 8; i++)
            *(float4*)(Og + (size_t)(qrow0 + ty + i * 16) * DH + tx * 4) = ov;
        return;
    }
    // ------------------------------------------------------------------------

    const uint32_t sb = smem_u32(smem);

    // cp.async tile ownership: row r (0..63), 32B chunk c within the 128B row
    const int r  = tid >> 2;
    const int cq = (tid & 3) * 16;           // element offset (16 bf16 = 32B)
    const size_t gsrc = (size_t)(bh * SQ) * DH + (size_t)r * DH + cq;
    const uint32_t dsto = r * ROWB + (tid & 3) * 32;

    // ---- prologue: issue tile kt=0 into buf0 ----
    {
        const uint32_t bb = sb + SM_KV0;
        cp16(bb + BK_HI + dsto,      g_khi + gsrc);
        cp16(bb + BK_HI + dsto + 16, g_khi + gsrc + 8);
        cp16(bb + BK_LO + dsto,      g_klo + gsrc);
        cp16(bb + BK_LO + dsto + 16, g_klo + gsrc + 8);
        cp16(bb + BV_HI + dsto,      g_vhi + gsrc);
        cp16(bb + BV_HI + dsto + 16, g_vhi + gsrc + 8);
        cp16(bb + BV_LO + dsto,      g_vlo + gsrc);
        cp16(bb + BV_LO + dsto + 16, g_vlo + gsrc + 8);
        CP_COMMIT();
    }

    // ---- Q -> bf16 hi/lo smem (overlaps tile-0 flight) ----
    {
        int row = tid >> 1, hf = tid & 1;
        const float* qr = Qg + (size_t)row * DH + hf * 32;
        char* qh = smem + SM_QHI + row * ROWB + hf * 64;
        char* ql = smem + SM_QLO + row * ROWB + hf * 64;
        #pragma unroll
        for (int i = 0; i < 4; i++) {
            float4 x = *(const float4*)(qr + i * 8);
            float4 y = *(const float4*)(qr + i * 8 + 4);
            uint4 H, L;
            split2(x.x, x.y, H.x, L.x); split2(x.z, x.w, H.y, L.y);
            split2(y.x, y.y, H.z, L.z); split2(y.z, y.w, H.w, L.w);
            *(uint4*)(qh + i * 16) = H;
            *(uint4*)(ql + i * 16) = L;
        }
    }

    const float C1 = 0.18033688011112042f;   // 0.125 * log2(e)
    const float C2 = 11.541560327111707f;    // 8 * log2(e) fixed shift
    const int m0 = warp * 16;

    float Oc[8][4];
    #pragma unroll
    for (int t = 0; t < 8; t++)
        #pragma unroll
        for (int c = 0; c < 4; c++) Oc[t][c] = 0.f;
    float l0 = 0.f, l1 = 0.f;

    const uint32_t qfb = sb + SM_QHI + (m0 + (lane & 15)) * ROWB + (lane >> 4) * 16;
    #define QLOFF (SM_QLO - SM_QHI)

    for (int kt = 0; kt < KV_TILES; kt++) {
        CP_WAIT0();
        __syncthreads();   // tile kt visible everywhere; GEMM(kt-1) reads done

        // ---- issue tile kt+1 into the other buffer (overlaps compute) ----
        if (kt + 1 < KV_TILES) {
            const uint32_t bb = sb + SM_KV0 + ((kt + 1) & 1) * KVBUF;
            const size_t gs = gsrc + (size_t)(kt + 1) * BN * DH;
            cp16(bb + BK_HI + dsto,      g_khi + gs);
            cp16(bb + BK_HI + dsto + 16, g_khi + gs + 8);
            cp16(bb + BK_LO + dsto,      g_klo + gs);
            cp16(bb + BK_LO + dsto + 16, g_klo + gs + 8);
            cp16(bb + BV_HI + dsto,      g_vhi + gs);
            cp16(bb + BV_HI + dsto + 16, g_vhi + gs + 8);
            cp16(bb + BV_LO + dsto,      g_vlo + gs);
            cp16(bb + BV_LO + dsto + 16, g_vlo + gs + 8);
            CP_COMMIT();
        }

        const uint32_t bufb = sb + SM_KV0 + (kt & 1) * KVBUF;
        const uint32_t kfb  = bufb + BK_HI + (lane & 7) * ROWB + (lane >> 3) * 16;
        const uint32_t vfb  = bufb + BV_HI + (lane & 15) * ROWB + (lane >> 4) * 16;

        // ---- GEMM1: S = Q @ K^T (3-split, ldmatrix fragments) ----
        float S[8][4];
        #pragma unroll
        for (int t = 0; t < 8; t++)
            #pragma unroll
            for (int c = 0; c < 4; c++) S[t][c] = 0.f;

        #pragma unroll
        for (int kcp = 0; kcp < 2; kcp++) {
            uint32_t qh0[4], qh1[4], ql0[4], ql1[4];
            ldmx4(qh0, qfb + kcp * 64);
            ldmx4(qh1, qfb + kcp * 64 + 32);
            ldmx4(ql0, qfb + QLOFF + kcp * 64);
            ldmx4(ql1, qfb + QLOFF + kcp * 64 + 32);
            #pragma unroll
            for (int nt = 0; nt < 8; nt++) {
                uint32_t kh[4], kl[4];
                ldmx4(kh, kfb + nt * (8 * ROWB) + kcp * 64);
                ldmx4(kl, kfb + (BK_LO - BK_HI) + nt * (8 * ROWB) + kcp * 64);
                mma_bf16(S[nt], qh0, kh[0], kh[1]);
                mma_bf16(S[nt], qh0, kl[0], kl[1]);
                mma_bf16(S[nt], ql0, kh[0], kh[1]);
                mma_bf16(S[nt], qh1, kh[2], kh[3]);
                mma_bf16(S[nt], qh1, kl[2], kl[3]);
                mma_bf16(S[nt], ql1, kh[2], kh[3]);
            }
        }

        // ---- softmax (fixed shift) + in-register P fragments ----
        uint32_t ah[4][4], al[4][4];
        #pragma unroll
        for (int nt = 0; nt < 8; nt++) {
            float p0 = ex2f(S[nt][0] * C1 - C2);
            float p1 = ex2f(S[nt][1] * C1 - C2);
            float p2 = ex2f(S[nt][2] * C1 - C2);
            float p3 = ex2f(S[nt][3] * C1 - C2);
            l0 += p0 + p1;
            l1 += p2 + p3;
            int kc = nt >> 1, o = (nt & 1) * 2;
            split2(p0, p1, ah[kc][o],     al[kc][o]);
            split2(p2, p3, ah[kc][o + 1], al[kc][o + 1]);
        }

        // ---- GEMM2: O += P @ V (V via ldmatrix.trans) ----
        #pragma unroll
        for (int kc = 0; kc < 4; kc++) {
            #pragma unroll
            for (int dtp = 0; dtp < 4; dtp++) {
                uint32_t va = kc * 16 * ROWB + dtp * 32;
                uint32_t h0, h1, h2, h3, q0, q1, q2, q3;
                ldmx4t(h0, h1, h2, h3, vfb + va);
                ldmx4t(q0, q1, q2, q3, vfb + (BV_LO - BV_HI) + va);
                mma_bf16(Oc[2 * dtp],     ah[kc], h0, h1);
                mma_bf16(Oc[2 * dtp + 1], ah[kc], h2, h3);
                mma_bf16(Oc[2 * dtp],     ah[kc], q0, q1);
                mma_bf16(Oc[2 * dtp + 1], ah[kc], q2, q3);
                mma_bf16(Oc[2 * dtp],     al[kc], h0, h1);
                mma_bf16(Oc[2 * dtp + 1], al[kc], h2, h3);
            }
        }
    }

    // ---- epilogue ----
    l0 += __shfl_xor_sync(0xffffffffu, l0, 1);
    l0 += __shfl_xor_sync(0xffffffffu, l0, 2);
    l1 += __shfl_xor_sync(0xffffffffu, l1, 1);
    l1 += __shfl_xor_sync(0xffffffffu, l1, 2);
    float inv0 = 1.0f / l0, inv1 = 1.0f / l1;

    float* r0p = Og + (size_t)(qrow0 + m0 + g) * DH + 2 * tg;
    float* r1p = r0p + 8 * (size_t)DH;
    #pragma unroll
    for (int dt = 0; dt < 8; dt++) {
        *(float2*)(r0p + dt * 8) = make_float2(Oc[dt][0] * inv0, Oc[dt][1] * inv0);
        *(float2*)(r1p + dt * 8) = make_float2(Oc[dt][2] * inv1, Oc[dt][3] * inv1);
    }
}

extern "C" void kernel_launch(void* const* d_in, const int* in_sizes, int n_in,
                              void* d_out, int out_size)
{
    const float* Q = (const float*)d_in[0];
    const float* K = (const float*)d_in[1];
    const float* V = (const float*)d_in[2];
    const int* mask = (const int*)d_in[3];
    float* O = (float*)d_out;

    conv_kv<<<8192, 256>>>(K, V, mask);

    cudaFuncSetAttribute(attn_mma,
                         cudaFuncAttributeMaxDynamicSharedMemorySize, SMEM_BYTES);
    dim3 grid(SQ / BM, 8 * 16);   // (8, 128)
    attn_mma<<<grid, NT, SMEM_BYTES>>>(Q, V, mask, O);
}